// round 5
// baseline (speedup 1.0000x reference)
#include <cuda_runtime.h>
#include <math.h>

#define BQ 8
#define NN 3072
#define HDIM 64
#define KNEI 16
#define BN (BQ*NN)

typedef unsigned long long u64;

// ---- scratch (device globals: allocation-free) ----
__device__ float g_h [BN*HDIM];
__device__ float g_h2[BN*HDIM];
__device__ float g_xx[BN];
__device__ int   g_idx[BN*KNEI];
__device__ float g_A[BN*128];
__device__ float g_C[BN*128];
__device__ float g_dist[(size_t)BN*NN];      // 302 MB d2 matrix [bq][c]
__device__ float g_pmax[BQ*24*64];

__device__ __forceinline__ float elu_f(float v){ return v > 0.f ? v : expm1f(v); }

__device__ __forceinline__ u64 ffma2(u64 a, u64 b, u64 c){
    u64 d; asm("fma.rn.f32x2 %0,%1,%2,%3;" : "=l"(d) : "l"(a), "l"(b), "l"(c)); return d;
}
__device__ __forceinline__ u64 packf2(float lo, float hi){
    u64 r; asm("mov.b64 %0,{%1,%2};" : "=l"(r) : "f"(lo), "f"(hi)); return r;
}
__device__ __forceinline__ float2 unpk(u64 v){
    float2 r; asm("mov.b64 {%0,%1},%2;" : "=f"(r.x), "=f"(r.y) : "l"(v)); return r;
}

// ---------------------------------------------------------------- embed (+ fused ||h||^2)
__global__ void __launch_bounds__(256) k_embed(const float* __restrict__ x, const float* __restrict__ dn,
                        const float* __restrict__ Wi, const float* __restrict__ bi)
{
    __shared__ float part[8];
    int i = blockIdx.x * 256 + threadIdx.x;
    int node = i >> 6, j = i & 63;
    float s = bi[j];
#pragma unroll
    for (int d = 0; d < 3; d++)
        s += x[node*3 + d] * dn[d] * Wi[d*HDIM + j];
    float hv = elu_f(s);
    g_h[i] = hv;
    float sq = hv * hv;
#pragma unroll
    for (int o = 16; o > 0; o >>= 1) sq += __shfl_xor_sync(0xffffffffu, sq, o);
    if ((threadIdx.x & 31) == 0) part[threadIdx.x >> 5] = sq;
    __syncthreads();
    if (threadIdx.x < 4)
        g_xx[blockIdx.x*4 + threadIdx.x] = part[2*threadIdx.x] + part[2*threadIdx.x + 1];
}

// ---------------------------------------------------------------- d2 matrix (symmetric tiles)
// grid (24, 24, BQ): qt, ct, b ; only ct >= qt does work, writes both orientations.
__global__ void __launch_bounds__(128) k_dist(int src)
{
    int qt = blockIdx.x, ct = blockIdx.y, b = blockIdx.z;
    if (ct < qt) return;
    const float* h = src ? g_h2 : g_h;
    __shared__ __align__(16) float sc[64*64];   // candidate subtile
    __shared__ float sxx[64];
    __shared__ float sd[128*33];                // stage (pad 33, odd)

    int tid = threadIdx.x;
    const float* hb = h + (size_t)b*NN*HDIM;
    int q = qt*128 + tid;

    u64 hq2[32];
    {
        const float4* p = (const float4*)(hb + (size_t)q*HDIM);
#pragma unroll
        for (int t = 0; t < 16; t++) {
            float4 v = p[t];
            hq2[2*t]   = packf2(v.x, v.y);
            hq2[2*t+1] = packf2(v.z, v.w);
        }
    }
    float qxx = g_xx[b*NN + q];

#pragma unroll 1
    for (int cs = 0; cs < 2; cs++) {
        int c0 = ct*128 + cs*64;
        __syncthreads();
        for (int i = tid; i < 64*64; i += 128) sc[i] = hb[(size_t)c0*HDIM + i];
        if (tid < 64) sxx[tid] = g_xx[b*NN + c0 + tid];
        __syncthreads();

#pragma unroll 1
        for (int ch = 0; ch < 2; ch++) {
            int cb = ch*32;
#pragma unroll 1
            for (int c = 0; c < 32; c++) {
                const ulonglong2* cv = (const ulonglong2*)(sc + (size_t)(cb + c)*64);
                u64 a0 = 0ull, a1 = 0ull, a2 = 0ull, a3 = 0ull;
#pragma unroll
                for (int t = 0; t < 16; t++) {
                    ulonglong2 m = cv[t];
                    if (t & 1) { a2 = ffma2(hq2[2*t], m.x, a2); a3 = ffma2(hq2[2*t+1], m.y, a3); }
                    else       { a0 = ffma2(hq2[2*t], m.x, a0); a1 = ffma2(hq2[2*t+1], m.y, a1); }
                }
                float2 f0 = unpk(a0), f1 = unpk(a1), f2 = unpk(a2), f3 = unpk(a3);
                float sum = ((f0.x+f0.y)+(f1.x+f1.y)) + ((f2.x+f2.y)+(f3.x+f3.y));
                sd[tid*33 + c] = qxx + sxx[cb + c] - 2.f*sum;
            }
            __syncthreads();
            {   // rows: dist[q0+r][c0+cb+cc]
                float* Dq = g_dist + ((size_t)(b*NN + qt*128))*NN + (c0 + cb);
                for (int i = tid; i < 128*32; i += 128) {
                    int r = i >> 5, cc = i & 31;
                    Dq[(size_t)r*NN + cc] = sd[r*33 + cc];
                }
            }
            if (ct != qt) {   // transposed: dist[c0+cb+cc][q0+r]
                float* Dc = g_dist + ((size_t)(b*NN + c0 + cb))*NN + qt*128;
                for (int i = tid; i < 32*128; i += 128) {
                    int cc = i >> 7, r = i & 127;
                    Dc[(size_t)cc*NN + r] = sd[r*33 + cc];
                }
            }
            __syncthreads();
        }
    }
}

// ---------------------------------------------------------------- top-16 selection (warp per query)
__global__ void __launch_bounds__(256) k_select()
{
    __shared__ float sval[8][32*17];
    __shared__ int   sidx[8][32*17];
    int wid = threadIdx.x >> 5, lane = threadIdx.x & 31;
    int q = blockIdx.x * 8 + wid;          // global query in [0, BN)
    const float* D = g_dist + (size_t)q*NN;

    float dist[KNEI]; int idxs[KNEI];
#pragma unroll
    for (int i = 0; i < KNEI; i++) { dist[i] = 3.0e38f; idxs[i] = 0x7fffffff; }

#pragma unroll 1
    for (int it = 0; it < 24; it++) {
        int c = it*128 + lane*4;
        float4 d4 = *(const float4*)(D + c);
        float dv[4] = {d4.x, d4.y, d4.z, d4.w};
#pragma unroll
        for (int u = 0; u < 4; u++) {
            float d2 = dv[u];
            if (d2 < dist[KNEI-1]) {
                int ci = c + u;
#pragma unroll
                for (int i = KNEI-1; i >= 0; i--) {
                    if (d2 < dist[i]) {
                        if (i < KNEI-1) { dist[i+1] = dist[i]; idxs[i+1] = idxs[i]; }
                        dist[i] = d2; idxs[i] = ci;
                    }
                }
            }
        }
    }

    // dump sorted per-lane lists (pad 17 -> conflict-free strided access)
#pragma unroll
    for (int i = 0; i < KNEI; i++) {
        sval[wid][lane*17 + i] = dist[i];
        sidx[wid][lane*17 + i] = idxs[i];
    }
    __syncwarp();

    // 16-round warp arg-min extraction, tie -> lower index (jax top_k stability)
    int head = 0;
    int* op = g_idx + (size_t)q*KNEI;
#pragma unroll 1
    for (int round = 0; round < KNEI; round++) {
        float v; int id;
        if (head < KNEI) { v = sval[wid][lane*17 + head]; id = sidx[wid][lane*17 + head]; }
        else             { v = 3.0e38f; id = 0x7fffffff; }
        float bv = v; int bi = id; int bl = lane;
#pragma unroll
        for (int o = 16; o > 0; o >>= 1) {
            float ov = __shfl_xor_sync(0xffffffffu, bv, o);
            int   oi = __shfl_xor_sync(0xffffffffu, bi, o);
            int   ol = __shfl_xor_sync(0xffffffffu, bl, o);
            if (ov < bv || (ov == bv && oi < bi)) { bv = ov; bi = oi; bl = ol; }
        }
        if (lane == bl) { head++; op[round] = bi; }
    }
}

// ---------------------------------------------------------------- per-node A/C precompute
__global__ void __launch_bounds__(1024) k_ac(int src, const float* __restrict__ W1l,
                                             const float* __restrict__ b1l)
{
    __shared__ __align__(16) u64 sW[8192];   // [half][d2][j] 64KB
    __shared__ u64 sh[8][32];
    const float* h = src ? g_h2 : g_h;
    int tid = threadIdx.x;

    for (int i = tid; i < 8192; i += 1024) {
        int half = i >> 12;
        int r = i & 4095;
        int d2 = r >> 7, j = r & 127;
        int d = half*64 + 2*d2;
        sW[i] = packf2(W1l[d*128 + j], W1l[(d+1)*128 + j]);
    }

    int j = tid & 127, nl = tid >> 7;
    float bj = b1l[j];
    size_t base = (size_t)blockIdx.x * 16;

#pragma unroll
    for (int pass = 0; pass < 2; pass++) {
        size_t n0 = base + pass*8;
        __syncthreads();
        if (tid < 256) {
            int nn = tid >> 5, d2 = tid & 31;
            const float* hp = h + (n0 + nn)*HDIM + 2*d2;
            sh[nn][d2] = packf2(hp[0], hp[1]);
        }
        __syncthreads();
        u64 a2 = 0ull, c2 = 0ull;
#pragma unroll
        for (int d2 = 0; d2 < 32; d2++) {
            u64 hv = sh[nl][d2];
            a2 = ffma2(hv, sW[d2*128 + j], a2);
            c2 = ffma2(hv, sW[4096 + d2*128 + j], c2);
        }
        float2 fa = unpk(a2), fc = unpk(c2);
        float c = fc.x + fc.y;
        float a = fa.x + fa.y;
        size_t node = n0 + nl;
        g_A[node*128 + j] = a - c + bj;
        g_C[node*128 + j] = c;
    }
}

// ---------------------------------------------------------------- edge aggregation (packed W2, fused xx)
__global__ void __launch_bounds__(256) k_edge(int dst, const float* __restrict__ W2l,
                                              const float* __restrict__ b2l)
{
    __shared__ __align__(16) u64 sW2p[64*66];       // [j][d2] pad 66 -> 33.8 KB
    __shared__ __align__(16) float sm1[4][16*128];  // 32 KB
    __shared__ float sxr[8];

    int tid   = threadIdx.x;
    int local = tid >> 6;
    int j     = tid & 63;
    size_t node = (size_t)blockIdx.x * 4 + local;
    int b     = (int)(node / NN);

    for (int i = tid; i < 64*64; i += 256) {
        int d2 = i >> 6, jj = i & 63;
        sW2p[jj*66 + d2] = packf2(W2l[(2*d2)*64 + jj], W2l[(2*d2+1)*64 + jj]);
    }

    const float* A = g_A + node*128;
    const int*  ip = g_idx + node*KNEI;
    float a0 = A[j], a1 = A[j + 64];
    int nbrs[KNEI];
#pragma unroll
    for (int k = 0; k < KNEI; k++) nbrs[k] = ip[k];
#pragma unroll 4
    for (int k = 0; k < KNEI; k++) {
        const float* C = g_C + ((size_t)(b*NN + nbrs[k]))*128;
        sm1[local][k*128 + j]      = elu_f(a0 + C[j]);
        sm1[local][k*128 + j + 64] = elu_f(a1 + C[j + 64]);
    }
    __syncthreads();

    u64 s2[KNEI];
#pragma unroll
    for (int k = 0; k < KNEI; k++) s2[k] = 0ull;

#pragma unroll 2
    for (int g = 0; g < 32; g++) {                  // 4 d's per group
        ulonglong2 w = *(const ulonglong2*)&sW2p[j*66 + 2*g];
#pragma unroll
        for (int k = 0; k < KNEI; k++) {
            ulonglong2 m = *(const ulonglong2*)&sm1[local][k*128 + 4*g];
            s2[k] = ffma2(m.x, w.x, s2[k]);
            s2[k] = ffma2(m.y, w.y, s2[k]);
        }
    }
    float bb = b2l[j];
    float acc = 0.f;
#pragma unroll
    for (int k = 0; k < KNEI; k++) {
        float2 f = unpk(s2[k]);
        acc += elu_f(f.x + f.y + bb);
    }

    float* hd = dst ? g_h2 : g_h;
    hd[node*HDIM + j] = acc;

    float sq = acc * acc;
#pragma unroll
    for (int o = 16; o > 0; o >>= 1) sq += __shfl_xor_sync(0xffffffffu, sq, o);
    if ((tid & 31) == 0) sxr[tid >> 5] = sq;
    __syncthreads();
    if (tid < 4)
        g_xx[blockIdx.x*4 + tid] = sxr[2*tid] + sxr[2*tid + 1];
}

// ---------------------------------------------------------------- two-stage maxpool
__global__ void k_pool()
{
    __shared__ float red[256];
    int b = blockIdx.y;
    int n0 = blockIdx.x * 128;
    int tid = threadIdx.x, j = tid & 63, r = tid >> 6;
    const float* h = g_h + ((size_t)b*NN + n0)*HDIM;
    float m = -3.0e38f;
    for (int n = r; n < 128; n += 4) m = fmaxf(m, h[(size_t)n*HDIM + j]);
    red[tid] = m;
    __syncthreads();
    if (tid < 64) {
        float mm = fmaxf(fmaxf(red[tid], red[64+tid]), fmaxf(red[128+tid], red[192+tid]));
        g_pmax[(b*24 + blockIdx.x)*64 + j] = mm;
    }
}

__global__ void k_final(const float* __restrict__ Wo1, const float* __restrict__ bo1,
                        const float* __restrict__ Wo2, const float* __restrict__ bo2,
                        const float* __restrict__ Wo3, const float* __restrict__ bo3,
                        float* __restrict__ out)
{
    __shared__ float pooled[64], o1[64], o2[64];
    int b = blockIdx.x, tid = threadIdx.x;
    float m = -3.0e38f;
#pragma unroll
    for (int p = 0; p < 24; p++) m = fmaxf(m, g_pmax[(b*24 + p)*64 + tid]);
    pooled[tid] = m;
    __syncthreads();
    {
        float s = bo1[tid];
#pragma unroll
        for (int d = 0; d < 64; d++) s += pooled[d] * Wo1[d*64 + tid];
        o1[tid] = elu_f(s);
    }
    __syncthreads();
    {
        float s = bo2[tid];
#pragma unroll
        for (int d = 0; d < 64; d++) s += o1[d] * Wo2[d*64 + tid];
        o2[tid] = elu_f(s);
    }
    __syncthreads();
    if (tid == 0) {
        float s = bo3[0];
#pragma unroll
        for (int d = 0; d < 64; d++) s += o2[d] * Wo3[d];
        out[b] = s;
    }
}

// ---------------------------------------------------------------- host
extern "C" void kernel_launch(void* const* d_in, const int* in_sizes, int n_in,
                              void* d_out, int out_size)
{
    const float* x   = (const float*)d_in[0];
    const float* dn  = (const float*)d_in[1];
    const float* Wi  = (const float*)d_in[2];
    const float* bi  = (const float*)d_in[3];
    const float* W1  = (const float*)d_in[4];
    const float* b1  = (const float*)d_in[5];
    const float* W2  = (const float*)d_in[6];
    const float* b2  = (const float*)d_in[7];
    const float* Wo1 = (const float*)d_in[8];
    const float* bo1 = (const float*)d_in[9];
    const float* Wo2 = (const float*)d_in[10];
    const float* bo2 = (const float*)d_in[11];
    const float* Wo3 = (const float*)d_in[12];
    const float* bo3 = (const float*)d_in[13];
    float* out = (float*)d_out;

    k_embed<<<BN*HDIM/256, 256>>>(x, dn, Wi, bi);

    for (int l = 0; l < 2; l++) {
        int src = l;
        int dst = 1 - l;
        k_ac    <<<BN/16, 1024>>>(src, W1 + l*128*128, b1 + l*128);
        k_dist  <<<dim3(24, 24, BQ), 128>>>(src);
        k_select<<<BN/8, 256>>>();
        k_edge  <<<BN/4, 256>>>(dst, W2 + l*128*64, b2 + l*64);
    }
    k_pool <<<dim3(24, BQ), 256>>>();
    k_final<<<BQ, 64>>>(Wo1, bo1, Wo2, bo2, Wo3, bo3, out);
}